// round 7
// baseline (speedup 1.0000x reference)
#include <cuda_runtime.h>

#define N_NODES 1000000
#define DEGREE 31
#define BLOCK 128
#define THRESH 16
#define NBLK ((N_NODES + BLOCK - 1) / BLOCK)    // 7813

__device__ float    g_p[N_NODES];
__device__ double   g_sum;
__device__ int      g_is64;
__device__ unsigned g_done = 0;

// Kernel 1: p = sigmoid(gains), vectorized. Block 0 warp 0 also detects the
// index dtype and zeroes the accumulator. N_NODES % 4 == 0.
__global__ void __launch_bounds__(256) prep_kernel(const float4* __restrict__ gains4,
                                                   const int* __restrict__ nb_raw) {
    int i = blockIdx.x * 256 + threadIdx.x;
    if (blockIdx.x == 0 && threadIdx.x < 32) {
        // int64 -> hi-words of first 32 elements are all 0 (indices < 2^20).
        // int32 -> those words are random indices in [0, 1e6): P(all 0) ~ 0.
        int hi = nb_raw[threadIdx.x * 2 + 1];
        unsigned all0 = __ballot_sync(0xffffffffu, hi == 0);
        if (threadIdx.x == 0) {
            g_is64 = (all0 == 0xffffffffu) ? 1 : 0;
            g_sum = 0.0;
        }
    }
    if (i < N_NODES / 4) {
        float4 x = gains4[i];
        float4 r;
        r.x = 1.0f / (1.0f + __expf(-x.x));
        r.y = 1.0f / (1.0f + __expf(-x.y));
        r.z = 1.0f / (1.0f + __expf(-x.z));
        r.w = 1.0f / (1.0f + __expf(-x.w));
        ((float4*)g_p)[i] = r;
    }
}

// Two-sided pruned Poisson-binomial DP. dp[16] is absorbing P(>=16).
// After trial j (0-based), state k is useful only if it can still reach 16:
// k >= j - 15; and reachable only if k <= j + 1.
__device__ __forceinline__ float dp_node(const float* __restrict__ pv) {
    float dp[THRESH + 1];
    dp[0] = 1.0f;
    #pragma unroll
    for (int k = 1; k <= THRESH; k++) dp[k] = 0.0f;

    #pragma unroll
    for (int j = 0; j < DEGREE + 1; j++) {
        const float pj = pv[j];
        if (j >= THRESH - 1)
            dp[THRESH] = fmaf(pj, dp[THRESH - 1], dp[THRESH]);   // absorb
        const int khi = (j + 1 < THRESH) ? (j + 1) : (THRESH - 1);
        const int klo = (j - 15 > 1) ? (j - 15) : 1;
        #pragma unroll
        for (int k = THRESH - 1; k >= 1; k--)
            if (k <= khi && k >= klo)
                dp[k] = fmaf(pj, dp[k - 1] - dp[k], dp[k]);
        if (j <= 15)
            dp[0] = dp[0] * (1.0f - pj);
    }
    return dp[THRESH];
}

// Kernel 2: warp-autonomous. Each warp stages its own 32 rows of indices
// (coalesced int4), __syncwarp, gathers p from the L2-resident table, runs the
// DP. No block-wide barrier in the hot path. N_NODES % 32 == 0, so every warp
// is fully active or fully idle.
__global__ void __launch_bounds__(BLOCK, 11) dp_kernel(const void* __restrict__ neighbors,
                                                       float* __restrict__ out) {
    __shared__ int   sidx[BLOCK * DEGREE];   // per-warp slices of 32*DEGREE
    __shared__ float sred[BLOCK / 32];

    const int tid  = threadIdx.x;
    const int wid  = tid >> 5;
    const int lane = tid & 31;
    const long long warpStart = (long long)blockIdx.x * BLOCK + wid * 32;

    float contrib = 0.0f;
    if (warpStart < N_NODES) {
        int* sw = sidx + wid * (32 * DEGREE);
        const long long elemBase = warpStart * (long long)DEGREE;

        // Stage this warp's 32x31 index rows, coalesced + vectorized.
        if (g_is64) {
            // 992 int64 = 496 int4 (low words at .x and .z).
            const int4* nb4 = (const int4*)((const long long*)neighbors + elemBase);
            #pragma unroll
            for (int t = lane; t < (32 * DEGREE) / 2; t += 32) {
                int4 v = nb4[t];
                sw[2 * t]     = v.x;
                sw[2 * t + 1] = v.z;
            }
        } else {
            // 992 int32 = 248 int4.
            const int4* nb4 = (const int4*)((const int*)neighbors + elemBase);
            #pragma unroll
            for (int t = lane; t < (32 * DEGREE) / 4; t += 32) {
                int4 v = nb4[t];
                sw[4 * t]     = v.x;
                sw[4 * t + 1] = v.y;
                sw[4 * t + 2] = v.z;
                sw[4 * t + 3] = v.w;
            }
        }
        __syncwarp();

        const int node = (int)(warpStart + lane);
        float pv[DEGREE + 1];
        pv[0] = g_p[node];
        #pragma unroll
        for (int j = 0; j < DEGREE; j++) {
            int idx = sw[lane * DEGREE + j];       // stride 31: bank-conflict-free
            idx = min(max(idx, 0), N_NODES - 1);   // crash-proofing
            pv[j + 1] = __ldg(&g_p[idx]);
        }
        contrib = dp_node(pv) - 0.25f * pv[0];
    }

    // Warp reduce -> block reduce -> one double atomic per block.
    #pragma unroll
    for (int o = 16; o; o >>= 1)
        contrib += __shfl_down_sync(0xffffffffu, contrib, o);
    if (lane == 0) sred[wid] = contrib;
    __syncthreads();
    if (tid < 32) {
        float v = (tid < BLOCK / 32) ? sred[tid] : 0.0f;
        #pragma unroll
        for (int o = 4; o; o >>= 1)
            v += __shfl_down_sync(0xffffffffu, v, o);
        if (tid == 0) {
            atomicAdd(&g_sum, (double)v);
            __threadfence();
            unsigned done = atomicAdd(&g_done, 1u);
            if (done == (unsigned)gridDim.x - 1u) {
                double s = atomicAdd(&g_sum, 0.0);   // L2-coherent read
                out[0] = -(float)s;
                g_done = 0;                           // reset for graph replays
            }
        }
    }
}

extern "C" void kernel_launch(void* const* d_in, const int* in_sizes, int n_in,
                              void* d_out, int out_size) {
    // Resolve input order from element counts (gains: 1M, neighbors: 31M).
    int gi = 0, ni = 1;
    if (in_sizes[0] != N_NODES) { gi = 1; ni = 0; }
    const float* gains     = (const float*)d_in[gi];
    const void*  neighbors = d_in[ni];
    float*       out       = (float*)d_out;

    prep_kernel<<<(N_NODES / 4 + 255) / 256, 256>>>((const float4*)gains,
                                                    (const int*)neighbors);
    dp_kernel<<<NBLK, BLOCK>>>(neighbors, out);
}

// round 8
// speedup vs baseline: 1.7813x; 1.7813x over previous
#include <cuda_runtime.h>

#define N_NODES 1000000
#define DEGREE 31
#define BLOCK 256
#define THRESH 16
#define TILES ((N_NODES + BLOCK - 1) / BLOCK)   // 3907

__device__ float    g_p[N_NODES];
__device__ double   g_sum;
__device__ int      g_is64;
__device__ unsigned g_done = 0;

// Kernel 1: p = sigmoid(gains), float4-vectorized (N_NODES % 4 == 0).
// Block 0 warp 0 also detects index dtype and zeroes the accumulator.
__global__ void __launch_bounds__(256) prep_kernel(const float4* __restrict__ gains4,
                                                   const int* __restrict__ nb_raw) {
    int i = blockIdx.x * 256 + threadIdx.x;
    if (blockIdx.x == 0 && threadIdx.x < 32) {
        // int64 -> hi-words of first 32 elements are all 0 (indices < 2^20).
        // int32 -> those words are random indices in [0, 1e6): P(all 0) ~ 0.
        int hi = nb_raw[threadIdx.x * 2 + 1];
        unsigned all0 = __ballot_sync(0xffffffffu, hi == 0);
        if (threadIdx.x == 0) {
            g_is64 = (all0 == 0xffffffffu) ? 1 : 0;
            g_sum = 0.0;
        }
    }
    if (i < N_NODES / 4) {
        float4 x = gains4[i];
        float4 r;
        r.x = 1.0f / (1.0f + __expf(-x.x));
        r.y = 1.0f / (1.0f + __expf(-x.y));
        r.z = 1.0f / (1.0f + __expf(-x.z));
        r.w = 1.0f / (1.0f + __expf(-x.w));
        ((float4*)g_p)[i] = r;
    }
}

// Per-thread Poisson-binomial DP with absorbing state at THRESH.
// NOTE: deliberately consumes the whole pv[] array in a uniform triangular
// pattern — this is the schedule under which ptxas front-batches all 31
// gather LDGs (MLP=31). Do NOT "optimize" this into a per-step load/use
// pipeline; that collapsed MLP and doubled runtime in R7.
__device__ __forceinline__ float dp_node(const float* __restrict__ pv) {
    float dp[THRESH + 1];
    dp[0] = 1.0f;
    #pragma unroll
    for (int k = 1; k <= THRESH; k++) dp[k] = 0.0f;

    #pragma unroll
    for (int j = 0; j < DEGREE + 1; j++) {
        const float pj = pv[j];
        const int kmax = (j + 1 < THRESH) ? (j + 1) : THRESH;  // triangular prune
        if (kmax == THRESH)
            dp[THRESH] = fmaf(pj, dp[THRESH - 1], dp[THRESH]); // absorbing state
        #pragma unroll
        for (int k = THRESH - 1; k >= 1; k--)
            if (k <= kmax)
                dp[k] = fmaf(pj, dp[k - 1] - dp[k], dp[k]);
        dp[0] = dp[0] * (1.0f - pj);
    }
    return dp[THRESH];
}

// Kernel 2: warp-autonomous. Each warp stages its own 32 rows of indices
// (coalesced int4), __syncwarp, gathers p from the L2-resident table, runs the
// DP. No block-wide barrier in the hot path. N_NODES % 32 == 0, so every warp
// is fully active or fully idle.
__global__ void __launch_bounds__(BLOCK) dp_kernel(const void* __restrict__ neighbors,
                                                   float* __restrict__ out) {
    __shared__ int   sidx[BLOCK * DEGREE];   // per-warp slices of 32*DEGREE
    __shared__ float sred[BLOCK / 32];

    const int tid  = threadIdx.x;
    const int wid  = tid >> 5;
    const int lane = tid & 31;
    const long long warpStart = (long long)blockIdx.x * BLOCK + wid * 32;

    float contrib = 0.0f;
    if (warpStart < N_NODES) {
        int* sw = sidx + wid * (32 * DEGREE);
        const long long elemBase = warpStart * (long long)DEGREE;

        // Stage this warp's 32x31 index rows, coalesced + vectorized.
        if (g_is64) {
            // 992 int64 = 496 int4 (low words at .x and .z).
            const int4* nb4 = (const int4*)((const long long*)neighbors + elemBase);
            #pragma unroll
            for (int t = lane; t < (32 * DEGREE) / 2; t += 32) {
                int4 v = nb4[t];
                sw[2 * t]     = v.x;
                sw[2 * t + 1] = v.z;
            }
        } else {
            // 992 int32 = 248 int4.
            const int4* nb4 = (const int4*)((const int*)neighbors + elemBase);
            #pragma unroll
            for (int t = lane; t < (32 * DEGREE) / 4; t += 32) {
                int4 v = nb4[t];
                sw[4 * t]     = v.x;
                sw[4 * t + 1] = v.y;
                sw[4 * t + 2] = v.z;
                sw[4 * t + 3] = v.w;
            }
        }
        __syncwarp();

        const int node = (int)(warpStart + lane);
        float pv[DEGREE + 1];
        pv[0] = g_p[node];
        #pragma unroll
        for (int j = 0; j < DEGREE; j++) {
            int idx = sw[lane * DEGREE + j];       // stride 31: bank-conflict-free
            idx = min(max(idx, 0), N_NODES - 1);   // crash-proofing
            pv[j + 1] = __ldg(&g_p[idx]);
        }
        __syncwarp();   // codegen pin: keep the 31 gathers batched before the DP

        contrib = dp_node(pv) - 0.25f * pv[0];
    }

    // Warp reduce -> block reduce -> one double atomic per block.
    #pragma unroll
    for (int o = 16; o; o >>= 1)
        contrib += __shfl_down_sync(0xffffffffu, contrib, o);
    if (lane == 0) sred[wid] = contrib;
    __syncthreads();
    if (tid < 32) {
        float v = (tid < BLOCK / 32) ? sred[tid] : 0.0f;
        #pragma unroll
        for (int o = 4; o; o >>= 1)
            v += __shfl_down_sync(0xffffffffu, v, o);
        if (tid == 0) {
            atomicAdd(&g_sum, (double)v);
            __threadfence();
            unsigned done = atomicAdd(&g_done, 1u);
            if (done == (unsigned)gridDim.x - 1u) {
                double s = atomicAdd(&g_sum, 0.0);   // L2-coherent read
                out[0] = -(float)s;
                g_done = 0;                           // reset for graph replays
            }
        }
    }
}

extern "C" void kernel_launch(void* const* d_in, const int* in_sizes, int n_in,
                              void* d_out, int out_size) {
    // Resolve input order from element counts (gains: 1M, neighbors: 31M).
    int gi = 0, ni = 1;
    if (in_sizes[0] != N_NODES) { gi = 1; ni = 0; }
    const float* gains     = (const float*)d_in[gi];
    const void*  neighbors = d_in[ni];
    float*       out       = (float*)d_out;

    prep_kernel<<<(N_NODES / 4 + 255) / 256, 256>>>((const float4*)gains,
                                                    (const int*)neighbors);
    dp_kernel<<<TILES, BLOCK>>>(neighbors, out);
}

// round 9
// speedup vs baseline: 1.9302x; 1.0836x over previous
#include <cuda_runtime.h>

#define N_NODES 1000000
#define DEGREE 31
#define BLOCK 256
#define THRESH 16
#define TILES ((N_NODES + BLOCK - 1) / BLOCK)   // 3907

__device__ float    g_p[N_NODES];
__device__ double   g_sum;
__device__ int      g_is64;
__device__ unsigned g_done = 0;

// Kernel 1: p = sigmoid(gains), float4-vectorized (N_NODES % 4 == 0).
// Block 0 warp 0 also detects index dtype and zeroes the accumulator.
__global__ void __launch_bounds__(256) prep_kernel(const float4* __restrict__ gains4,
                                                   const int* __restrict__ nb_raw) {
    int i = blockIdx.x * 256 + threadIdx.x;
    if (blockIdx.x == 0 && threadIdx.x < 32) {
        // int64 -> hi-words of first 32 elements are all 0 (indices < 2^20).
        // int32 -> those words are random indices in [0, 1e6): P(all 0) ~ 0.
        int hi = nb_raw[threadIdx.x * 2 + 1];
        unsigned all0 = __ballot_sync(0xffffffffu, hi == 0);
        if (threadIdx.x == 0) {
            g_is64 = (all0 == 0xffffffffu) ? 1 : 0;
            g_sum = 0.0;
        }
    }
    if (i < N_NODES / 4) {
        float4 x = gains4[i];
        float4 r;
        r.x = 1.0f / (1.0f + __expf(-x.x));
        r.y = 1.0f / (1.0f + __expf(-x.y));
        r.z = 1.0f / (1.0f + __expf(-x.z));
        r.w = 1.0f / (1.0f + __expf(-x.w));
        ((float4*)g_p)[i] = r;
    }
}

// Per-thread Poisson-binomial DP with absorbing state at THRESH.
// SCHEDULE-SENSITIVE: this exact form (triangular prune only, whole pv[]
// consumed inside, called right after the gather loop with NO intervening
// sync) is what makes ptxas front-batch all 31 gather LDGs (regs=44, MLP=31).
// Pruned variants (R7) and an extra __syncwarp before the call (R8) both
// re-scheduled to regs=40 with pipelined loads and cost +10..110 us.
__device__ __forceinline__ float dp_node(const float* __restrict__ pv) {
    float dp[THRESH + 1];
    dp[0] = 1.0f;
    #pragma unroll
    for (int k = 1; k <= THRESH; k++) dp[k] = 0.0f;

    #pragma unroll
    for (int j = 0; j < DEGREE + 1; j++) {
        const float pj = pv[j];
        const int kmax = (j + 1 < THRESH) ? (j + 1) : THRESH;  // triangular prune
        if (kmax == THRESH)
            dp[THRESH] = fmaf(pj, dp[THRESH - 1], dp[THRESH]); // absorbing state
        #pragma unroll
        for (int k = THRESH - 1; k >= 1; k--)
            if (k <= kmax)
                dp[k] = fmaf(pj, dp[k - 1] - dp[k], dp[k]);
        dp[0] = dp[0] * (1.0f - pj);
    }
    return dp[THRESH];
}

// Kernel 2: warp-autonomous (byte-exact R5 hot path). Each warp stages its own
// 32 rows of indices (coalesced int4), __syncwarp, gathers p from the
// L2-resident table, runs the DP. No block-wide barrier in the hot path.
__global__ void __launch_bounds__(BLOCK) dp_kernel(const void* __restrict__ neighbors,
                                                   float* __restrict__ out) {
    __shared__ int   sidx[BLOCK * DEGREE];   // per-warp slices of 32*DEGREE
    __shared__ float sred[BLOCK / 32];

    const int tid  = threadIdx.x;
    const int wid  = tid >> 5;
    const int lane = tid & 31;
    const long long warpStart = (long long)blockIdx.x * BLOCK + wid * 32;

    float contrib = 0.0f;
    if (warpStart < N_NODES) {
        int* sw = sidx + wid * (32 * DEGREE);
        const long long elemBase = warpStart * (long long)DEGREE;

        // Stage this warp's 32x31 index rows, coalesced + vectorized.
        if (g_is64) {
            // 992 int64 = 496 int4 (low words at .x and .z).
            const int4* nb4 = (const int4*)((const long long*)neighbors + elemBase);
            #pragma unroll
            for (int t = lane; t < (32 * DEGREE) / 2; t += 32) {
                int4 v = nb4[t];
                sw[2 * t]     = v.x;
                sw[2 * t + 1] = v.z;
            }
        } else {
            // 992 int32 = 248 int4.
            const int4* nb4 = (const int4*)((const int*)neighbors + elemBase);
            #pragma unroll
            for (int t = lane; t < (32 * DEGREE) / 4; t += 32) {
                int4 v = nb4[t];
                sw[4 * t]     = v.x;
                sw[4 * t + 1] = v.y;
                sw[4 * t + 2] = v.z;
                sw[4 * t + 3] = v.w;
            }
        }
        __syncwarp();

        const int node = (int)(warpStart + lane);
        float pv[DEGREE + 1];
        pv[0] = g_p[node];
        #pragma unroll
        for (int j = 0; j < DEGREE; j++) {
            int idx = sw[lane * DEGREE + j];       // stride 31: bank-conflict-free
            idx = min(max(idx, 0), N_NODES - 1);   // crash-proofing
            pv[j + 1] = __ldg(&g_p[idx]);
        }
        contrib = dp_node(pv) - 0.25f * pv[0];
    }

    // Warp reduce -> block reduce -> one double atomic per block.
    #pragma unroll
    for (int o = 16; o; o >>= 1)
        contrib += __shfl_down_sync(0xffffffffu, contrib, o);
    if (lane == 0) sred[wid] = contrib;
    __syncthreads();
    if (tid < 32) {
        float v = (tid < BLOCK / 32) ? sred[tid] : 0.0f;
        #pragma unroll
        for (int o = 4; o; o >>= 1)
            v += __shfl_down_sync(0xffffffffu, v, o);
        if (tid == 0) {
            atomicAdd(&g_sum, (double)v);
            __threadfence();
            unsigned done = atomicAdd(&g_done, 1u);
            if (done == (unsigned)gridDim.x - 1u) {
                double s = atomicAdd(&g_sum, 0.0);   // L2-coherent read
                out[0] = -(float)s;
                g_done = 0;                           // reset for graph replays
            }
        }
    }
}

extern "C" void kernel_launch(void* const* d_in, const int* in_sizes, int n_in,
                              void* d_out, int out_size) {
    // Resolve input order from element counts (gains: 1M, neighbors: 31M).
    int gi = 0, ni = 1;
    if (in_sizes[0] != N_NODES) { gi = 1; ni = 0; }
    const float* gains     = (const float*)d_in[gi];
    const void*  neighbors = d_in[ni];
    float*       out       = (float*)d_out;

    prep_kernel<<<(N_NODES / 4 + 255) / 256, 256>>>((const float4*)gains,
                                                    (const int*)neighbors);
    dp_kernel<<<TILES, BLOCK>>>(neighbors, out);
}

// round 10
// speedup vs baseline: 1.9633x; 1.0172x over previous
#include <cuda_runtime.h>

#define N_NODES 1000000
#define DEGREE 31
#define BLOCK 256
#define THRESH 16
#define TILES ((N_NODES + BLOCK - 1) / BLOCK)   // 3907

__device__ float    g_p[N_NODES];
__device__ double   g_sum;
__device__ int      g_is64;
__device__ unsigned g_done = 0;

// Kernel 1: p = sigmoid(gains), float4-vectorized (N_NODES % 4 == 0).
// Block 0 warp 0 also detects index dtype and zeroes the accumulator.
// Triggers programmatic launch completion so dp_kernel can start staging early.
__global__ void __launch_bounds__(256) prep_kernel(const float4* __restrict__ gains4,
                                                   const int* __restrict__ nb_raw) {
    int i = blockIdx.x * 256 + threadIdx.x;
    if (blockIdx.x == 0 && threadIdx.x < 32) {
        // int64 -> hi-words of first 32 elements are all 0 (indices < 2^20).
        // int32 -> those words are random indices in [0, 1e6): P(all 0) ~ 0.
        int hi = nb_raw[threadIdx.x * 2 + 1];
        unsigned all0 = __ballot_sync(0xffffffffu, hi == 0);
        if (threadIdx.x == 0) {
            g_is64 = (all0 == 0xffffffffu) ? 1 : 0;
            g_sum = 0.0;
        }
    }
    if (i < N_NODES / 4) {
        float4 x = gains4[i];
        float4 r;
        r.x = 1.0f / (1.0f + __expf(-x.x));
        r.y = 1.0f / (1.0f + __expf(-x.y));
        r.z = 1.0f / (1.0f + __expf(-x.z));
        r.w = 1.0f / (1.0f + __expf(-x.w));
        ((float4*)g_p)[i] = r;
    }
    cudaTriggerProgrammaticLaunchCompletion();
}

// Per-thread Poisson-binomial DP with absorbing state at THRESH.
// SCHEDULE-SENSITIVE (see R7/R8 post-mortems): this exact form, called right
// after the gather loop with NO intervening sync, makes ptxas front-batch all
// 31 gather LDGs (regs=44, MLP=31, L1=86%). regs=40 in ncu means the schedule
// broke (pipelined loads) and costs +10..110 us. Do not restructure.
__device__ __forceinline__ float dp_node(const float* __restrict__ pv) {
    float dp[THRESH + 1];
    dp[0] = 1.0f;
    #pragma unroll
    for (int k = 1; k <= THRESH; k++) dp[k] = 0.0f;

    #pragma unroll
    for (int j = 0; j < DEGREE + 1; j++) {
        const float pj = pv[j];
        const int kmax = (j + 1 < THRESH) ? (j + 1) : THRESH;  // triangular prune
        if (kmax == THRESH)
            dp[THRESH] = fmaf(pj, dp[THRESH - 1], dp[THRESH]); // absorbing state
        #pragma unroll
        for (int k = THRESH - 1; k >= 1; k--)
            if (k <= kmax)
                dp[k] = fmaf(pj, dp[k - 1] - dp[k], dp[k]);
        dp[0] = dp[0] * (1.0f - pj);
    }
    return dp[THRESH];
}

// Kernel 2: warp-autonomous (R9 hot path). Stages indices (independent of
// g_p), then grid-dependency-syncs on prep, then gathers + DP. The PDL sync
// sits at the same point as the staging __syncwarp — NOT between gather and
// DP (R8 showed a fence there breaks the LDG batch).
__global__ void __launch_bounds__(BLOCK) dp_kernel(const void* __restrict__ neighbors,
                                                   float* __restrict__ out) {
    __shared__ int   sidx[BLOCK * DEGREE];   // per-warp slices of 32*DEGREE
    __shared__ float sred[BLOCK / 32];

    const int tid  = threadIdx.x;
    const int wid  = tid >> 5;
    const int lane = tid & 31;
    const long long warpStart = (long long)blockIdx.x * BLOCK + wid * 32;

    float contrib = 0.0f;
    if (warpStart < N_NODES) {
        int* sw = sidx + wid * (32 * DEGREE);
        const long long elemBase = warpStart * (long long)DEGREE;

        // g_is64 is set by prep's block 0 before any g_p store; reading it here
        // is safe even pre-sync only if prep block 0 ran. To be strictly safe
        // under PDL, sync BEFORE reading g_is64 (it is prep output too).
        cudaGridDependencySynchronize();

        // Stage this warp's 32x31 index rows, coalesced + vectorized.
        if (g_is64) {
            // 992 int64 = 496 int4 (low words at .x and .z).
            const int4* nb4 = (const int4*)((const long long*)neighbors + elemBase);
            #pragma unroll
            for (int t = lane; t < (32 * DEGREE) / 2; t += 32) {
                int4 v = nb4[t];
                sw[2 * t]     = v.x;
                sw[2 * t + 1] = v.z;
            }
        } else {
            // 992 int32 = 248 int4.
            const int4* nb4 = (const int4*)((const int*)neighbors + elemBase);
            #pragma unroll
            for (int t = lane; t < (32 * DEGREE) / 4; t += 32) {
                int4 v = nb4[t];
                sw[4 * t]     = v.x;
                sw[4 * t + 1] = v.y;
                sw[4 * t + 2] = v.z;
                sw[4 * t + 3] = v.w;
            }
        }
        __syncwarp();

        const int node = (int)(warpStart + lane);
        float pv[DEGREE + 1];
        pv[0] = g_p[node];
        #pragma unroll
        for (int j = 0; j < DEGREE; j++) {
            int idx = sw[lane * DEGREE + j];       // stride 31: bank-conflict-free
            idx = min(max(idx, 0), N_NODES - 1);   // crash-proofing
            pv[j + 1] = __ldg(&g_p[idx]);
        }
        contrib = dp_node(pv) - 0.25f * pv[0];
    } else {
        cudaGridDependencySynchronize();
    }

    // Warp reduce -> block reduce -> one double atomic per block.
    #pragma unroll
    for (int o = 16; o; o >>= 1)
        contrib += __shfl_down_sync(0xffffffffu, contrib, o);
    if (lane == 0) sred[wid] = contrib;
    __syncthreads();
    if (tid < 32) {
        float v = (tid < BLOCK / 32) ? sred[tid] : 0.0f;
        #pragma unroll
        for (int o = 4; o; o >>= 1)
            v += __shfl_down_sync(0xffffffffu, v, o);
        if (tid == 0) {
            atomicAdd(&g_sum, (double)v);
            __threadfence();
            unsigned done = atomicAdd(&g_done, 1u);
            if (done == (unsigned)gridDim.x - 1u) {
                double s = atomicAdd(&g_sum, 0.0);   // L2-coherent read
                out[0] = -(float)s;
                g_done = 0;                           // reset for graph replays
            }
        }
    }
}

extern "C" void kernel_launch(void* const* d_in, const int* in_sizes, int n_in,
                              void* d_out, int out_size) {
    // Resolve input order from element counts (gains: 1M, neighbors: 31M).
    int gi = 0, ni = 1;
    if (in_sizes[0] != N_NODES) { gi = 1; ni = 0; }
    const float* gains     = (const float*)d_in[gi];
    const void*  neighbors = d_in[ni];
    float*       out       = (float*)d_out;

    prep_kernel<<<(N_NODES / 4 + 255) / 256, 256>>>((const float4*)gains,
                                                    (const int*)neighbors);

    // PDL: dp may launch while prep drains; it grid-syncs before reading g_p.
    cudaLaunchConfig_t cfg = {};
    cfg.gridDim  = dim3(TILES, 1, 1);
    cfg.blockDim = dim3(BLOCK, 1, 1);
    cudaLaunchAttribute attrs[1];
    attrs[0].id = cudaLaunchAttributeProgrammaticStreamSerialization;
    attrs[0].val.programmaticStreamSerializationAllowed = 1;
    cfg.attrs = attrs;
    cfg.numAttrs = 1;
    cudaLaunchKernelEx(&cfg, dp_kernel, (const void*)neighbors, out);
}

// round 11
// speedup vs baseline: 1.9643x; 1.0005x over previous
#include <cuda_runtime.h>

#define N_NODES 1000000
#define DEGREE 31
#define BLOCK 256
#define THRESH 16
#define TILES ((N_NODES + BLOCK - 1) / BLOCK)   // 3907

__device__ float    g_p[N_NODES];
__device__ double   g_sum;
__device__ unsigned g_done = 0;

// Kernel 1: p = sigmoid(gains), float4-vectorized (N_NODES % 4 == 0).
// Block 0 also zeroes the accumulator. Triggers programmatic launch completion
// so dp_kernel can overlap its index staging with this kernel.
__global__ void __launch_bounds__(256) prep_kernel(const float4* __restrict__ gains4) {
    int i = blockIdx.x * 256 + threadIdx.x;
    if (blockIdx.x == 0 && threadIdx.x == 0) g_sum = 0.0;
    if (i < N_NODES / 4) {
        float4 x = gains4[i];
        float4 r;
        r.x = 1.0f / (1.0f + __expf(-x.x));
        r.y = 1.0f / (1.0f + __expf(-x.y));
        r.z = 1.0f / (1.0f + __expf(-x.z));
        r.w = 1.0f / (1.0f + __expf(-x.w));
        ((float4*)g_p)[i] = r;
    }
    cudaTriggerProgrammaticLaunchCompletion();
}

// Per-thread Poisson-binomial DP with absorbing state at THRESH.
// SCHEDULE-SENSITIVE (see R7/R8 post-mortems): this exact form, called right
// after the gather loop with NO intervening sync, makes ptxas front-batch all
// 31 gather LDGs (regs=44, MLP=31, L1=86%). regs=40 in ncu means the schedule
// broke (pipelined loads) and costs +10..110 us. Do not restructure.
__device__ __forceinline__ float dp_node(const float* __restrict__ pv) {
    float dp[THRESH + 1];
    dp[0] = 1.0f;
    #pragma unroll
    for (int k = 1; k <= THRESH; k++) dp[k] = 0.0f;

    #pragma unroll
    for (int j = 0; j < DEGREE + 1; j++) {
        const float pj = pv[j];
        const int kmax = (j + 1 < THRESH) ? (j + 1) : THRESH;  // triangular prune
        if (kmax == THRESH)
            dp[THRESH] = fmaf(pj, dp[THRESH - 1], dp[THRESH]); // absorbing state
        #pragma unroll
        for (int k = THRESH - 1; k >= 1; k--)
            if (k <= kmax)
                dp[k] = fmaf(pj, dp[k - 1] - dp[k], dp[k]);
        dp[0] = dp[0] * (1.0f - pj);
    }
    return dp[THRESH];
}

// Kernel 2: warp-autonomous. Each warp detects the index dtype LOCALLY
// (depends only on `neighbors`, not on prep), stages its 32x31 indices
// coalesced into smem, THEN grid-syncs on prep, then gathers + DP.
// The PDL sync sits with the staging __syncwarp — NOT between gather and DP
// (R8 showed a fence there breaks the LDG batch).
__global__ void __launch_bounds__(BLOCK) dp_kernel(const void* __restrict__ neighbors,
                                                   float* __restrict__ out) {
    __shared__ int   sidx[BLOCK * DEGREE];   // per-warp slices of 32*DEGREE
    __shared__ float sred[BLOCK / 32];

    const int tid  = threadIdx.x;
    const int wid  = tid >> 5;
    const int lane = tid & 31;
    const long long warpStart = (long long)blockIdx.x * BLOCK + wid * 32;

    float contrib = 0.0f;
    if (warpStart < N_NODES) {
        int* sw = sidx + wid * (32 * DEGREE);
        const long long elemBase = warpStart * (long long)DEGREE;

        // Local dtype detection: if int64, hi-words of the first 32 elements
        // are all 0 (indices < 2^20); if int32, those words are uniform random
        // indices in [0, 1e6): P(all 0) ~ 0. L2-hot after the first warp.
        int hi = ((const int*)neighbors)[lane * 2 + 1];
        unsigned all0 = __ballot_sync(0xffffffffu, hi == 0);
        const bool is64 = (all0 == 0xffffffffu);

        // Stage this warp's 32x31 index rows, coalesced + vectorized.
        if (is64) {
            // 992 int64 = 496 int4 (low words at .x and .z).
            const int4* nb4 = (const int4*)((const long long*)neighbors + elemBase);
            #pragma unroll
            for (int t = lane; t < (32 * DEGREE) / 2; t += 32) {
                int4 v = nb4[t];
                sw[2 * t]     = v.x;
                sw[2 * t + 1] = v.z;
            }
        } else {
            // 992 int32 = 248 int4.
            const int4* nb4 = (const int4*)((const int*)neighbors + elemBase);
            #pragma unroll
            for (int t = lane; t < (32 * DEGREE) / 4; t += 32) {
                int4 v = nb4[t];
                sw[4 * t]     = v.x;
                sw[4 * t + 1] = v.y;
                sw[4 * t + 2] = v.z;
                sw[4 * t + 3] = v.w;
            }
        }
        cudaGridDependencySynchronize();   // prep's g_p must be visible below
        __syncwarp();

        const int node = (int)(warpStart + lane);
        float pv[DEGREE + 1];
        pv[0] = g_p[node];
        #pragma unroll
        for (int j = 0; j < DEGREE; j++) {
            int idx = sw[lane * DEGREE + j];       // stride 31: bank-conflict-free
            idx = min(max(idx, 0), N_NODES - 1);   // crash-proofing
            pv[j + 1] = __ldg(&g_p[idx]);
        }
        contrib = dp_node(pv) - 0.25f * pv[0];
    } else {
        cudaGridDependencySynchronize();
    }

    // Warp reduce -> block reduce -> one double atomic per block.
    #pragma unroll
    for (int o = 16; o; o >>= 1)
        contrib += __shfl_down_sync(0xffffffffu, contrib, o);
    if (lane == 0) sred[wid] = contrib;
    __syncthreads();
    if (tid < 32) {
        float v = (tid < BLOCK / 32) ? sred[tid] : 0.0f;
        #pragma unroll
        for (int o = 4; o; o >>= 1)
            v += __shfl_down_sync(0xffffffffu, v, o);
        if (tid == 0) {
            atomicAdd(&g_sum, (double)v);
            __threadfence();
            unsigned done = atomicAdd(&g_done, 1u);
            if (done == (unsigned)gridDim.x - 1u) {
                double s = atomicAdd(&g_sum, 0.0);   // L2-coherent read
                out[0] = -(float)s;
                g_done = 0;                           // reset for graph replays
            }
        }
    }
}

extern "C" void kernel_launch(void* const* d_in, const int* in_sizes, int n_in,
                              void* d_out, int out_size) {
    // Resolve input order from element counts (gains: 1M, neighbors: 31M).
    int gi = 0, ni = 1;
    if (in_sizes[0] != N_NODES) { gi = 1; ni = 0; }
    const float* gains     = (const float*)d_in[gi];
    const void*  neighbors = d_in[ni];
    float*       out       = (float*)d_out;

    prep_kernel<<<(N_NODES / 4 + 255) / 256, 256>>>((const float4*)gains);

    // PDL: dp launches while prep drains; it grid-syncs before reading g_p.
    cudaLaunchConfig_t cfg = {};
    cfg.gridDim  = dim3(TILES, 1, 1);
    cfg.blockDim = dim3(BLOCK, 1, 1);
    cudaLaunchAttribute attrs[1];
    attrs[0].id = cudaLaunchAttributeProgrammaticStreamSerialization;
    attrs[0].val.programmaticStreamSerializationAllowed = 1;
    cfg.attrs = attrs;
    cfg.numAttrs = 1;
    cudaLaunchKernelEx(&cfg, dp_kernel, (const void*)neighbors, out);
}